// round 14
// baseline (speedup 1.0000x reference)
#include <cuda_runtime.h>
#include <cstdint>

#define LOG2E  1.4426950408889634f
#define LN2    0.6931471805599453f
#define SP     256            // padded extended-label stride (S <= 256)
#define NWORK  592            // worker blocks (4 per SM)
#define RPI    (NWORK * 8)    // rows per sweep (warp-per-row)
#define FDSTRIDE 8            // g_frame_done stride (ints) -> 32B apart

__device__ __forceinline__ float ex2(float x) {
    float y; asm("ex2.approx.ftz.f32 %0, %1;" : "=f"(y) : "f"(x)); return y;
}
__device__ __forceinline__ float lg2(float x) {
    float y; asm("lg2.approx.f32 %0, %1;" : "=f"(y) : "f"(x)); return y;
}
__device__ __forceinline__ float exp2i(int d) {          // 2^d, d in [-126,127]
    return __int_as_float((127 + d) << 23);
}
__device__ __forceinline__ int ld_acq(const int* p) {    // acquire load (gpu scope)
    int v;
    asm volatile("ld.acquire.gpu.global.b32 %0, [%1];" : "=r"(v) : "l"(p) : "memory");
    return v;
}

// scratch: p_ext [B][T][SP] (true softmax probs <= 1, zero-padded) + pad for
// unguarded prefetch; per-frame completion counters (32B-strided); costs.
#define MAX_LP (32 * 1000 * SP + 4096)
__device__ float g_lp[MAX_LP];
__device__ float g_costs[128];
__device__ int   g_frame_done[1024 * FDSTRIDE];

// ---------------------------------------------------------------------------
// Kernel 0: reset the per-frame completion counters (graph replays reuse them)
// ---------------------------------------------------------------------------
__global__ void reset_kernel() {
    for (int i = threadIdx.x; i < 1024 * FDSTRIDE; i += 256) g_frame_done[i] = 0;
}

// ---------------------------------------------------------------------------
// Kernel 1: FUSED producer/consumer.
//  blocks [0, B):   DP consumers, one warp per utterance (warps 1-7 exit).
//  blocks [B, ...): workers — warp-per-row logsumexp+gather in t-major order;
//                   after each row: threadfence + atomicAdd(g_frame_done[t]).
//  DP gates on acquire-load polls (with __nanosleep backoff) of g_frame_done,
//  pipelined one 8-step group ahead; frames stream through a 16-slot
//  cp.async smem ring where each lane self-copies exactly the 32 bytes it
//  later reads (per-thread wait_group -> no syncwarp needed for the data).
//  All 624 blocks are co-resident (<= 1184 slots) -> workers always progress
//  -> polls terminate; no deadlock is possible.
// ---------------------------------------------------------------------------
__global__ void __launch_bounds__(256)
fused_kernel(const float* __restrict__ act,
             const int*   __restrict__ targets,
             const int*   __restrict__ in_len,
             const int*   __restrict__ tg_len,
             int T, int B, int C, int L, int S) {
    __shared__ float ring[16 * SP];      // 16KB, used by DP path only

    if ((int)blockIdx.x >= B) {
        // ================= worker path (producer) =================
        const int warp = threadIdx.x >> 5;
        const int lane = threadIdx.x & 31;
        const int TB = T * B;
        for (int r = ((int)blockIdx.x - B) * 8 + warp; r < TB; r += RPI) {
            const int t = r / B;
            const int b = r - t * B;
            const float* row = act + (size_t)r * C;
            const int C4 = C >> 2;
            const float4* row4 = (const float4*)row;

            float acc0 = 0.f, acc1 = 0.f, acc2 = 0.f, acc3 = 0.f;
            int i = lane;
            for (; i + 96 < C4; i += 128) {
                float4 v0 = row4[i];
                float4 v1 = row4[i + 32];
                float4 v2 = row4[i + 64];
                float4 v3 = row4[i + 96];
                acc0 += (ex2(v0.x * LOG2E) + ex2(v0.y * LOG2E))
                      + (ex2(v0.z * LOG2E) + ex2(v0.w * LOG2E));
                acc1 += (ex2(v1.x * LOG2E) + ex2(v1.y * LOG2E))
                      + (ex2(v1.z * LOG2E) + ex2(v1.w * LOG2E));
                acc2 += (ex2(v2.x * LOG2E) + ex2(v2.y * LOG2E))
                      + (ex2(v2.z * LOG2E) + ex2(v2.w * LOG2E));
                acc3 += (ex2(v3.x * LOG2E) + ex2(v3.y * LOG2E))
                      + (ex2(v3.z * LOG2E) + ex2(v3.w * LOG2E));
            }
            for (; i < C4; i += 32) {
                float4 v = row4[i];
                acc0 += (ex2(v.x * LOG2E) + ex2(v.y * LOG2E))
                      + (ex2(v.z * LOG2E) + ex2(v.w * LOG2E));
            }
            for (int j = (C4 << 2) + lane; j < C; j += 32)
                acc1 += ex2(row[j] * LOG2E);

            float sum = (acc0 + acc1) + (acc2 + acc3);
            #pragma unroll
            for (int o = 16; o; o >>= 1) sum += __shfl_xor_sync(~0u, sum, o);
            const float lse2 = lg2(sum);

            float* outp = g_lp + ((size_t)b * T + t) * SP;
            const int* tg = targets + b * L;
            #pragma unroll
            for (int k = 0; k < SP / 32; k++) {
                const int s = lane + 32 * k;
                float val = 0.f;
                if (s < S) {
                    int col = (s & 1) ? tg[s >> 1] : 0;
                    val = ex2(fmaf(row[col], LOG2E, -lse2));
                }
                outp[s] = val;
            }
            // publish frame completion (release pattern)
            __threadfence();
            __syncwarp();
            if (lane == 0) atomicAdd(&g_frame_done[t * FDSTRIDE], 1);
        }
        return;
    }

    // ================= DP path (consumer) =================
    if (threadIdx.x >= 32) return;
    const int b    = blockIdx.x;
    const int lane = threadIdx.x;
    const int s0   = lane << 3;

    float skm1, skm3, skm5, skm7;
    {
        const int* tg = targets + b * L;
        #define SKF(sv, dst) { int li = (sv) >> 1;                         \
            if (li >= L) dst = 0.f;                                        \
            else if (li == 0) dst = 1.f;                                   \
            else dst = (tg[li] != tg[li - 1]) ? 1.f : 0.f; }
        SKF(s0 + 1, skm1); SKF(s0 + 3, skm3); SKF(s0 + 5, skm5); SKF(s0 + 7, skm7);
        #undef SKF
    }

    const int len    = in_len[b];
    const int s_last = 2 * tg_len[b];
    const int Bc     = B;
    const int* fd    = g_frame_done;

    #define POLL(frame) do {                                               \
        if (lane == 0) {                                                   \
            int g = 0;                                                     \
            while (ld_acq(fd + (frame) * FDSTRIDE) < Bc                    \
                   && ++g < (1 << 20))                                     \
                __nanosleep(200);                                          \
        }                                                                  \
        __syncwarp();                                                      \
    } while (0)

    // initial gate: frame 0 init + preload of frames 1..8
    POLL(min(8, len - 1));

    // t = 0 init (all lanes broadcast-load the same 8 bytes)
    float a[8];
    {
        const float2* p0 = (const float2*)(g_lp + (size_t)b * T * SP);
        float2 q = p0[0];
        a[0] = (lane == 0) ? q.x : 0.f;
        a[1] = (lane == 0) ? q.y : 0.f;
        #pragma unroll
        for (int k = 2; k < 8; k++) a[k] = 0.f;
    }
    float h = 0.f, hscale = 1.f;
    int   E = 0;

    unsigned rbase = (unsigned)__cvta_generic_to_shared(ring);
    const char* gsrc = (const char*)(g_lp + (size_t)b * T * SP + s0);

    #define CPA2(f) do {                                                   \
        unsigned ds = rbase + (((f) & 15) << 10) + (lane << 5);            \
        const char* gs = gsrc + (size_t)(f) * (SP * 4);                    \
        asm volatile("cp.async.ca.shared.global [%0], [%1], 16;\n\t"       \
                     "cp.async.ca.shared.global [%2], [%3], 16;\n\t"       \
                     "cp.async.commit_group;"                              \
                     :: "r"(ds), "l"(gs), "r"(ds + 16), "l"(gs + 16)       \
                     : "memory"); } while (0)
    #define WAITG(n) asm volatile("cp.async.wait_group %0;" :: "n"(n) : "memory")

    #define STEP(L0, L1) do {                                              \
        float hv = h * hscale;                                             \
        float n0 = (a[0] + hv)                    * (L0).x;                \
        float n1 = fmaf(hv,   skm1, a[1] + a[0])  * (L0).y;                \
        float n2 = (a[2] + a[1])                  * (L0).z;                \
        float n3 = fmaf(a[1], skm3, a[3] + a[2])  * (L0).w;                \
        float n4 = (a[4] + a[3])                  * (L1).x;                \
        float n5 = fmaf(a[3], skm5, a[5] + a[4])  * (L1).y;                \
        float n6 = (a[6] + a[5])                  * (L1).z;                \
        float n7 = fmaf(a[5], skm7, a[7] + a[6])  * (L1).w;                \
        a[0]=n0; a[1]=n1; a[2]=n2; a[3]=n3;                                \
        a[4]=n4; a[5]=n5; a[6]=n6; a[7]=n7;                                \
        h = __shfl_up_sync(0xffffffffu, n7, 1);                            \
        if (lane == 0) h = 0.f;                                            \
    } while (0)

    #define RENORM() do {                                                  \
        float m = fmaxf(fmaxf(fmaxf(a[0],a[1]), fmaxf(a[2],a[3])),        \
                        fmaxf(fmaxf(a[4],a[5]), fmaxf(a[6],a[7])));        \
        int eb = (__float_as_int(m) >> 23) & 255;                          \
        bool actv = (eb != 0);                                             \
        int Et = E + (actv ? (eb - 127) : 0);                              \
        int EprevT = __shfl_up_sync(0xffffffffu, Et, 1);                   \
        if (lane == 0) EprevT = Et;                                        \
        int En = actv ? (Et > EprevT ? Et : EprevT) : EprevT;              \
        int diff = E - En;                                                 \
        diff = diff > 126 ? 126 : diff;                                    \
        float sc = (diff < -126) ? 0.f : exp2i(diff);                      \
        _Pragma("unroll")                                                  \
        for (int k = 0; k < 8; k++) a[k] *= sc;                            \
        E = En;                                                            \
        float sc_prev = __shfl_up_sync(0xffffffffu, sc, 1);                \
        h *= sc_prev;                                                      \
        int Enp = __shfl_up_sync(0xffffffffu, En, 1);                      \
        int d2 = Enp - En;                                                 \
        d2 = d2 > 60 ? 60 : d2;                                            \
        hscale = (d2 < -126) ? 0.f : exp2i(d2);                            \
        if (lane == 0) hscale = 1.f;                                       \
    } while (0)

    // preload frames 1..8 into the ring
    #pragma unroll
    for (int f = 1; f <= 8; f++) CPA2(f);
    WAITG(6);                                     // frames <= 2 arrived
    float4 curA, curB;
    {
        const float4* sp = (const float4*)(ring + (1 << 8) + s0);
        curA = sp[0]; curB = sp[1];               // frame 1
    }

    int t = 1;
    for (; t + 7 <= len - 1; t += 8) {
        // gate: this group issues loads for frames t+8..t+15
        POLL(min(t + 15, len - 1));

        #pragma unroll
        for (int j = 0; j < 8; j++) {
            const int u = t + j;
            WAITG(6);                              // frame u+1 arrived
            float4 nA, nB;
            {
                const float4* sp = (const float4*)(ring + (((u + 1) & 15) << 8) + s0);
                nA = sp[0]; nB = sp[1];
            }
            CPA2(u + 8);
            STEP(curA, curB);
            curA = nA; curB = nB;
            if (j == 3 || j == 7) RENORM();
        }
    }
    // tail: <= 7 remaining steps (all frames already issued + gated)
    WAITG(0);
    while (t <= len - 1) {
        STEP(curA, curB);
        t++;
        if (t <= len - 1) {
            const float4* sp = (const float4*)(ring + ((t & 15) << 8) + s0);
            curA = sp[0]; curB = sp[1];
        }
    }
    RENORM();                                      // normalize before capture

    // capture alpha_{len-1}[s_last], [s_last-1] (+ lane exponents)
    const int sb = s_last, sl = s_last - 1;
    float vb = a[0], vl = a[0];
    #pragma unroll
    for (int k = 1; k < 8; k++) {
        vb = ((sb & 7) == k) ? a[k] : vb;
        vl = ((sl & 7) == k) ? a[k] : vl;
    }
    float ab = __shfl_sync(0xffffffffu, vb, sb >> 3);
    float al = __shfl_sync(0xffffffffu, vl, sl >> 3);
    int   Eb = __shfl_sync(0xffffffffu, E,  sb >> 3);
    int   El = __shfl_sync(0xffffffffu, E,  sl >> 3);

    if (lane == 0) {
        float c2b = lg2(ab) + (float)Eb;
        float c2l = lg2(al) + (float)El;
        float hi = fmaxf(c2b, c2l), lo = fminf(c2b, c2l);
        float dd = fmaxf(lo - hi, -126.f);
        float c2 = hi + lg2(1.f + ex2(dd));
        g_costs[b] = -c2 * LN2;
    }
    #undef STEP
    #undef RENORM
    #undef CPA2
    #undef WAITG
    #undef POLL
}

// ---------------------------------------------------------------------------
// Kernel 2: final scalar: sum(costs) / B / sum(target_lengths)
// ---------------------------------------------------------------------------
__global__ void finalize_kernel(const int* __restrict__ tg_len, int B,
                                float* __restrict__ out) {
    const int tid = threadIdx.x;
    float cs = 0.f, ts = 0.f;
    for (int b = tid; b < B; b += 32) {
        cs += g_costs[b];
        ts += (float)tg_len[b];
    }
    #pragma unroll
    for (int o = 16; o; o >>= 1) {
        cs += __shfl_xor_sync(~0u, cs, o);
        ts += __shfl_xor_sync(~0u, ts, o);
    }
    if (tid == 0) out[0] = cs / (float)B / ts;
}

extern "C" void kernel_launch(void* const* d_in, const int* in_sizes, int n_in,
                              void* d_out, int out_size) {
    const float* act     = (const float*)d_in[0];   // [T,B,C]
    const int*   targets = (const int*)d_in[1];     // [B*L]
    const int*   in_len  = (const int*)d_in[2];     // [B]
    const int*   tg_len  = (const int*)d_in[3];     // [B]

    const int B = in_sizes[2];
    const int L = in_sizes[1] / B;
    const int T = 1000;
    const int C = in_sizes[0] / (B * T);
    const int S = 2 * L + 1;

    reset_kernel<<<1, 256>>>();
    fused_kernel<<<B + NWORK, 256>>>(act, targets, in_len, tg_len, T, B, C, L, S);
    finalize_kernel<<<1, 32>>>(tg_len, B, (float*)d_out);
}

// round 15
// speedup vs baseline: 2.4453x; 2.4453x over previous
#include <cuda_runtime.h>
#include <cstdint>

#define LOG2E  1.4426950408889634f
#define LN2    0.6931471805599453f
#define SP     256            // padded extended-label stride (S <= 256)

__device__ __forceinline__ float ex2(float x) {
    float y; asm("ex2.approx.ftz.f32 %0, %1;" : "=f"(y) : "f"(x)); return y;
}
__device__ __forceinline__ float lg2(float x) {
    float y; asm("lg2.approx.f32 %0, %1;" : "=f"(y) : "f"(x)); return y;
}
__device__ __forceinline__ float exp2i(int d) {          // 2^d, d in [-126,127]
    return __int_as_float((127 + d) << 23);
}

// scratch: p_ext [B][T][SP] (true softmax probs <= 1, zero-padded).
// +8192 pad floats so the DP's unguarded distance-8 prefetch (up to 15
// frames past len) can never read out of bounds; values never consumed.
#define MAX_LP (32 * 1000 * SP + 8192)
__device__ float g_lp[MAX_LP];
__device__ float g_costs[128];
__device__ int   g_done;          // self-resetting completion counter

// ---------------------------------------------------------------------------
// Kernel A: WARP-PER-ROW logsumexp + gather, MLP=8 batched float4 loads.
// Emits true probabilities p = 2^(x*log2e - lse2) <= 1 (pad positions 0.0).
// ---------------------------------------------------------------------------
__global__ void __launch_bounds__(256)
lse_gather_kernel(const float* __restrict__ act,
                  const int*   __restrict__ targets,
                  int T, int B, int C, int L, int S) {
    const int warp = threadIdx.x >> 5;
    const int lane = threadIdx.x & 31;
    const int r    = blockIdx.x * 8 + warp;       // row index = t*B + b
    if (r >= T * B) return;
    const int t = r / B;
    const int b = r - t * B;
    const float* row = act + (size_t)r * C;

    const int C4 = C >> 2;
    const float4* row4 = (const float4*)row;

    float acc0 = 0.f, acc1 = 0.f, acc2 = 0.f, acc3 = 0.f;
    int i = lane;
    // strips of 8 batched loads (MLP=8)
    for (; i + 224 < C4; i += 256) {
        float4 v0 = row4[i];
        float4 v1 = row4[i + 32];
        float4 v2 = row4[i + 64];
        float4 v3 = row4[i + 96];
        float4 v4 = row4[i + 128];
        float4 v5 = row4[i + 160];
        float4 v6 = row4[i + 192];
        float4 v7 = row4[i + 224];
        acc0 += (ex2(v0.x * LOG2E) + ex2(v0.y * LOG2E))
              + (ex2(v0.z * LOG2E) + ex2(v0.w * LOG2E));
        acc1 += (ex2(v1.x * LOG2E) + ex2(v1.y * LOG2E))
              + (ex2(v1.z * LOG2E) + ex2(v1.w * LOG2E));
        acc2 += (ex2(v2.x * LOG2E) + ex2(v2.y * LOG2E))
              + (ex2(v2.z * LOG2E) + ex2(v2.w * LOG2E));
        acc3 += (ex2(v3.x * LOG2E) + ex2(v3.y * LOG2E))
              + (ex2(v3.z * LOG2E) + ex2(v3.w * LOG2E));
        acc0 += (ex2(v4.x * LOG2E) + ex2(v4.y * LOG2E))
              + (ex2(v4.z * LOG2E) + ex2(v4.w * LOG2E));
        acc1 += (ex2(v5.x * LOG2E) + ex2(v5.y * LOG2E))
              + (ex2(v5.z * LOG2E) + ex2(v5.w * LOG2E));
        acc2 += (ex2(v6.x * LOG2E) + ex2(v6.y * LOG2E))
              + (ex2(v6.z * LOG2E) + ex2(v6.w * LOG2E));
        acc3 += (ex2(v7.x * LOG2E) + ex2(v7.y * LOG2E))
              + (ex2(v7.z * LOG2E) + ex2(v7.w * LOG2E));
    }
    // strips of 4
    for (; i + 96 < C4; i += 128) {
        float4 v0 = row4[i];
        float4 v1 = row4[i + 32];
        float4 v2 = row4[i + 64];
        float4 v3 = row4[i + 96];
        acc0 += (ex2(v0.x * LOG2E) + ex2(v0.y * LOG2E))
              + (ex2(v0.z * LOG2E) + ex2(v0.w * LOG2E));
        acc1 += (ex2(v1.x * LOG2E) + ex2(v1.y * LOG2E))
              + (ex2(v1.z * LOG2E) + ex2(v1.w * LOG2E));
        acc2 += (ex2(v2.x * LOG2E) + ex2(v2.y * LOG2E))
              + (ex2(v2.z * LOG2E) + ex2(v2.w * LOG2E));
        acc3 += (ex2(v3.x * LOG2E) + ex2(v3.y * LOG2E))
              + (ex2(v3.z * LOG2E) + ex2(v3.w * LOG2E));
    }
    for (; i < C4; i += 32) {
        float4 v = row4[i];
        acc0 += (ex2(v.x * LOG2E) + ex2(v.y * LOG2E))
              + (ex2(v.z * LOG2E) + ex2(v.w * LOG2E));
    }
    for (int j = (C4 << 2) + lane; j < C; j += 32)
        acc1 += ex2(row[j] * LOG2E);

    float sum = (acc0 + acc1) + (acc2 + acc3);
    #pragma unroll
    for (int o = 16; o; o >>= 1) sum += __shfl_xor_sync(~0u, sum, o);
    const float lse2 = lg2(sum);                  // logsumexp, log2 domain

    float* outp = g_lp + ((size_t)b * T + t) * SP;
    const int* tg = targets + b * L;
    #pragma unroll
    for (int k = 0; k < SP / 32; k++) {
        const int s = lane + 32 * k;
        float val = 0.f;
        if (s < S) {
            int col = (s & 1) ? tg[s >> 1] : 0;
            val = ex2(fmaf(row[col], LOG2E, -lse2));
        }
        outp[s] = val;
    }
}

// ---------------------------------------------------------------------------
// Kernel B: alpha recursion, LINEAR domain, per-lane block floating point.
// One warp per utterance, 8 alphas per lane, own exponent E per lane;
// branchless renorm every 4 steps. In-place register ring of 8 frames
// (prefetch distance 8, zero ring moves). Steady-state: pure FMA pipe.
// Last-finishing block also computes the final scalar (threadfence +
// self-resetting atomic counter) — no separate finalize launch.
// ---------------------------------------------------------------------------
__global__ void __launch_bounds__(32, 1)
ctc_dp_kernel(const int* __restrict__ targets,
              const int* __restrict__ in_len,
              const int* __restrict__ tg_len,
              int T, int B, int L, int S,
              float* __restrict__ out) {
    const int b    = blockIdx.x;
    const int lane = threadIdx.x;
    const int s0   = lane << 3;

    float skm1, skm3, skm5, skm7;
    {
        const int* tg = targets + b * L;
        #define SKF(sv, dst) { int li = (sv) >> 1;                         \
            if (li >= L) dst = 0.f;                                        \
            else if (li == 0) dst = 1.f;                                   \
            else dst = (tg[li] != tg[li - 1]) ? 1.f : 0.f; }
        SKF(s0 + 1, skm1); SKF(s0 + 3, skm3); SKF(s0 + 5, skm5); SKF(s0 + 7, skm7);
        #undef SKF
    }

    const int len    = in_len[b];
    const int s_last = 2 * tg_len[b];
    const float* base = g_lp + (size_t)b * T * SP + s0;

    // t = 0 init (linear): only s = 0, 1 live
    float a[8];
    {
        const float4* p = (const float4*)base;
        float4 q0 = p[0];
        a[0] = (s0 == 0) ? q0.x : 0.f;
        a[1] = (lane == 0) ? q0.y : 0.f;
        #pragma unroll
        for (int k = 2; k < 8; k++) a[k] = 0.f;
    }
    float h = 0.f, hscale = 1.f;
    int   E = 0;

    #define STEP(L0, L1) do {                                              \
        float hv = h * hscale;                                             \
        float n0 = (a[0] + hv)                    * (L0).x;                \
        float n1 = fmaf(hv,   skm1, a[1] + a[0])  * (L0).y;                \
        float n2 = (a[2] + a[1])                  * (L0).z;                \
        float n3 = fmaf(a[1], skm3, a[3] + a[2])  * (L0).w;                \
        float n4 = (a[4] + a[3])                  * (L1).x;                \
        float n5 = fmaf(a[3], skm5, a[5] + a[4])  * (L1).y;                \
        float n6 = (a[6] + a[5])                  * (L1).z;                \
        float n7 = fmaf(a[5], skm7, a[7] + a[6])  * (L1).w;                \
        a[0]=n0; a[1]=n1; a[2]=n2; a[3]=n3;                                \
        a[4]=n4; a[5]=n5; a[6]=n6; a[7]=n7;                                \
        h = __shfl_up_sync(0xffffffffu, n7, 1);                            \
        if (lane == 0) h = 0.f;                                            \
    } while (0)

    #define LDQ(da, db, tt) { const float4* p =                            \
        (const float4*)(base + (size_t)(tt) * SP); da = p[0]; db = p[1]; }

    #define RENORM() do {                                                  \
        float m = fmaxf(fmaxf(fmaxf(a[0],a[1]), fmaxf(a[2],a[3])),        \
                        fmaxf(fmaxf(a[4],a[5]), fmaxf(a[6],a[7])));        \
        int eb = (__float_as_int(m) >> 23) & 255;                          \
        bool actv = (eb != 0);                                             \
        int Et = E + (actv ? (eb - 127) : 0);                              \
        int EprevT = __shfl_up_sync(0xffffffffu, Et, 1);                   \
        if (lane == 0) EprevT = Et;                                        \
        int En = actv ? (Et > EprevT ? Et : EprevT) : EprevT;              \
        int diff = E - En;                                                 \
        diff = diff > 126 ? 126 : diff;                                    \
        float sc = (diff < -126) ? 0.f : exp2i(diff);                      \
        _Pragma("unroll")                                                  \
        for (int k = 0; k < 8; k++) a[k] *= sc;                            \
        E = En;                                                            \
        float sc_prev = __shfl_up_sync(0xffffffffu, sc, 1);                \
        h *= sc_prev;                                                      \
        int Enp = __shfl_up_sync(0xffffffffu, En, 1);                      \
        int d2 = Enp - En;                                                 \
        d2 = d2 > 60 ? 60 : d2;                                            \
        hscale = (d2 < -126) ? 0.f : exp2i(d2);                            \
        if (lane == 0) hscale = 1.f;                                       \
    } while (0)

    // ring preload: slot j holds frame t+j (t starts at 1), distance 8
    float4 ra[8], rb[8];
    #pragma unroll
    for (int j = 0; j < 8; j++) LDQ(ra[j], rb[j], 1 + j);

    int t = 1;
    for (; t + 7 <= len - 1; t += 8) {
        #pragma unroll
        for (int j = 0; j < 8; j++) {
            STEP(ra[j], rb[j]);
            LDQ(ra[j], rb[j], t + 8 + j);   // in-place reload, used 8 steps later
            if (j == 3 || j == 7) RENORM();
        }
    }
    // tail: slot j still holds frame t+j; <= 7 steps remain
    {
        int rem = (len - 1) - t + 1;         // 0..7
        if (rem > 0) { STEP(ra[0], rb[0]); }
        if (rem > 1) { STEP(ra[1], rb[1]); }
        if (rem > 2) { STEP(ra[2], rb[2]); }
        if (rem > 3) { STEP(ra[3], rb[3]); }
        if (rem > 4) { STEP(ra[4], rb[4]); }
        if (rem > 5) { STEP(ra[5], rb[5]); }
        if (rem > 6) { STEP(ra[6], rb[6]); }
    }
    RENORM();                                // normalize before capture

    // capture alpha_{len-1}[s_last], [s_last-1] (+ lane exponents)
    const int sb = s_last, sl = s_last - 1;
    float vb = a[0], vl = a[0];
    #pragma unroll
    for (int k = 1; k < 8; k++) {
        vb = ((sb & 7) == k) ? a[k] : vb;
        vl = ((sl & 7) == k) ? a[k] : vl;
    }
    float ab = __shfl_sync(0xffffffffu, vb, sb >> 3);
    float al = __shfl_sync(0xffffffffu, vl, sl >> 3);
    int   Eb = __shfl_sync(0xffffffffu, E,  sb >> 3);
    int   El = __shfl_sync(0xffffffffu, E,  sl >> 3);

    if (lane == 0) {
        float c2b = lg2(ab) + (float)Eb;
        float c2l = lg2(al) + (float)El;
        float hi = fmaxf(c2b, c2l), lo = fminf(c2b, c2l);
        float dd = fmaxf(lo - hi, -126.f);
        float c2 = hi + lg2(1.f + ex2(dd));
        g_costs[b] = -c2 * LN2;
    }

    // ---- inline finalize: last block to finish reduces g_costs ----
    __threadfence();
    int done = 0;
    if (lane == 0) done = (atomicAdd(&g_done, 1) == B - 1) ? 1 : 0;
    done = __shfl_sync(0xffffffffu, done, 0);
    if (done) {
        __threadfence();                     // make other blocks' costs visible
        float cs = 0.f, ts = 0.f;
        if (lane < B) {
            cs = g_costs[lane];
            ts = (float)tg_len[lane];
        }
        #pragma unroll
        for (int o = 16; o; o >>= 1) {
            cs += __shfl_xor_sync(~0u, cs, o);
            ts += __shfl_xor_sync(~0u, ts, o);
        }
        if (lane == 0) {
            out[0] = cs / (float)B / ts;
            g_done = 0;                      // self-reset for graph replays
            __threadfence();
        }
    }
    #undef STEP
    #undef LDQ
    #undef RENORM
}

extern "C" void kernel_launch(void* const* d_in, const int* in_sizes, int n_in,
                              void* d_out, int out_size) {
    const float* act     = (const float*)d_in[0];   // [T,B,C]
    const int*   targets = (const int*)d_in[1];     // [B*L]
    const int*   in_len  = (const int*)d_in[2];     // [B]
    const int*   tg_len  = (const int*)d_in[3];     // [B]

    const int B = in_sizes[2];
    const int L = in_sizes[1] / B;
    const int T = 1000;
    const int C = in_sizes[0] / (B * T);
    const int S = 2 * L + 1;

    const int rows = T * B;
    lse_gather_kernel<<<(rows + 7) / 8, 256>>>(act, targets, T, B, C, L, S);
    ctc_dp_kernel<<<B, 32>>>(targets, in_len, tg_len, T, B, L, S, (float*)d_out);
}